// round 7
// baseline (speedup 1.0000x reference)
#include <cuda_runtime.h>

// ---------------------------------------------------------------------------
// AdaptiveUnivariateFunction — fused persistent kernel (round 7).
//   xn = (x - min)/(max - min + 1e-6) in [0,1)
//   out = cp[idx] + t*(cp[idx+1]-cp[idx]),  idx=clamp(floor(xn*31),0,30)
//
// Reuse ladder across the grid barrier (persistent blocks keep SMEM+L2):
//   top ~29MB of x  -> stashed in SMEM during phase 1 (zero re-read traffic)
//   next 96MB       -> pinned in L2 (evict_last)
//   rest            -> streamed (.cs), re-read from DRAM in phase 2
// Phase 2 walks each thread's own indices in REVERSE: SMEM slots first,
// then pinned L2 window, then DRAM. Stores are .cs (never displace pins).
// ---------------------------------------------------------------------------

#define NPART 1184              // 148 SMs x 8 blocks -> exactly one wave
#define NTHREADS 256
#define NKEEP 6                 // float4s kept in SMEM per thread (24 KB/block)
#define PIN_V4 6291456          // 96 MB / 16 B pinned in L2 (round-5 optimum)

// ping-pong (min,max) accumulators in flipped-uint space; slot = epoch & 1
__device__ unsigned int g_mm[2][2] = {{0xFFFFFFFFu, 0u}, {0xFFFFFFFFu, 0u}};
__device__ float2 g_sb[2];               // published (S, B) per slot
__device__ unsigned int g_count;         // barrier arrivals
__device__ unsigned int g_release;       // barrier epoch (monotone)

__device__ __forceinline__ unsigned int ld_acq(const unsigned int* p) {
    unsigned int v;
    asm volatile("ld.global.acquire.gpu.u32 %0, [%1];" : "=r"(v) : "l"(p));
    return v;
}
__device__ __forceinline__ unsigned int flipf(float f) {
    unsigned int u = __float_as_uint(f);
    return u ^ ((unsigned int)(-(int)(u >> 31)) | 0x80000000u);
}
__device__ __forceinline__ float unflipf(unsigned int u) {
    return __uint_as_float(u ^ (((u >> 31) - 1u) | 0x80000000u));
}
__device__ __forceinline__ float4 ld_pin(const float4* p, unsigned long long pol) {
    float4 v;
    asm volatile("ld.global.L2::cache_hint.v4.f32 {%0,%1,%2,%3}, [%4], %5;"
                 : "=f"(v.x), "=f"(v.y), "=f"(v.z), "=f"(v.w)
                 : "l"(p), "l"(pol));
    return v;
}

__device__ __forceinline__ float auf_eval(float x, float S, float B,
                                          const float2* __restrict__ tab) {
    float xn31 = fmaf(x, S, B);          // xn * 31
    int idx = (int)xn31;                 // trunc == floor here
    idx = max(0, min(idx, 30));          // boundary rounding value-neutral
    float2 ad = tab[idx];                // (cp[idx], cp[idx+1]-cp[idx])
    return fmaf(xn31 - (float)idx, ad.y, ad.x);
}

__global__ void __launch_bounds__(NTHREADS, 8)
auf_fused_kernel(const float* __restrict__ xs,
                 const float* __restrict__ cp,
                 float* __restrict__ outs,
                 int n) {
    extern __shared__ float4 skeep[];    // NKEEP * NTHREADS float4s (24 KB)
    __shared__ float2 tab[32];
    __shared__ float smin[8], smax[8];
    __shared__ float s_SB[2];

    // epoch (pre-arrival read is safe: release needs THIS block's arrival)
    unsigned int epoch0 = 0;
    if (threadIdx.x == 0) epoch0 = ld_acq(&g_release);

    // spline table: (cp[i], cp[i+1]-cp[i]); slot 31 duplicates 30
    if (threadIdx.x < 32) {
        int i = (threadIdx.x < 31) ? (int)threadIdx.x : 30;
        float c0 = cp[i];
        float c1 = cp[i + 1];
        tab[threadIdx.x] = make_float2(c0, c1 - c0);
    }

    unsigned long long pol;
    asm volatile("createpolicy.fractional.L2::evict_last.b64 %0, 1.0;" : "=l"(pol));

    const float4* __restrict__ x4 = (const float4*)xs;
    const int nv4 = n >> 2;
    const int tid0 = blockIdx.x * NTHREADS + (int)threadIdx.x;
    const int stride = NPART * NTHREADS;

    // per-thread index layout (reverse-replayed in phase 2)
    const int jlast   = tid0 + ((nv4 - 1 - tid0) / stride) * stride; // tid0<nv4 here
    const int keep_lo = jlast - (NKEEP - 1) * stride;   // first SMEM-kept index
    const int keep_span = NKEEP * stride;
    int pin_lo = nv4 - keep_span - PIN_V4;              // global pin window start
    if (pin_lo < 0) pin_lo = 0;

    // ------------------- phase 1: min/max -------------------
    float vmin = 3.402823466e38f;
    float vmax = -3.402823466e38f;

    int i = tid0;
    // streaming region
    #pragma unroll 4
    for (; i < pin_lo && i < keep_lo; i += stride) {
        float4 v = __ldcs(&x4[i]);
        vmin = fminf(vmin, fminf(fminf(v.x, v.y), fminf(v.z, v.w)));
        vmax = fmaxf(vmax, fmaxf(fmaxf(v.x, v.y), fmaxf(v.z, v.w)));
    }
    // pinned L2 window
    #pragma unroll 4
    for (; i < keep_lo; i += stride) {
        float4 v = ld_pin(&x4[i], pol);
        vmin = fminf(vmin, fminf(fminf(v.x, v.y), fminf(v.z, v.w)));
        vmax = fmaxf(vmax, fmaxf(fmaxf(v.x, v.y), fmaxf(v.z, v.w)));
    }
    // SMEM-kept region (.cs: SMEM is the cache, keep L2 clean)
    {
        int slot = (i - keep_lo) / stride;              // 0 in the normal case
        for (; i < nv4; i += stride, slot++) {
            float4 v = __ldcs(&x4[i]);
            skeep[slot * NTHREADS + threadIdx.x] = v;
            vmin = fminf(vmin, fminf(fminf(v.x, v.y), fminf(v.z, v.w)));
            vmax = fmaxf(vmax, fmaxf(fmaxf(v.x, v.y), fmaxf(v.z, v.w)));
        }
    }
    if (blockIdx.x == 0 && threadIdx.x < (n & 3)) {     // scalar tail (defensive)
        float v = xs[(nv4 << 2) + threadIdx.x];
        vmin = fminf(vmin, v);
        vmax = fmaxf(vmax, v);
    }

    #pragma unroll
    for (int o = 16; o; o >>= 1) {
        vmin = fminf(vmin, __shfl_xor_sync(0xFFFFFFFFu, vmin, o));
        vmax = fmaxf(vmax, __shfl_xor_sync(0xFFFFFFFFu, vmax, o));
    }
    const int wid = threadIdx.x >> 5;
    if ((threadIdx.x & 31) == 0) { smin[wid] = vmin; smax[wid] = vmax; }
    __syncthreads();

    // ------------------- barrier with folded reduction -------------------
    if (threadIdx.x == 0) {
        float bmin = smin[0], bmax = smax[0];
        #pragma unroll
        for (int w = 1; w < 8; w++) {
            bmin = fminf(bmin, smin[w]);
            bmax = fmaxf(bmax, smax[w]);
        }
        const int s = (int)(epoch0 & 1u);
        atomicMin(&g_mm[s][0], flipf(bmin));
        atomicMax(&g_mm[s][1], flipf(bmax));
        __threadfence();
        unsigned int old = atomicAdd(&g_count, 1u);
        if (old == NPART - 1) {
            float fmin = unflipf(ld_acq(&g_mm[s][0]));
            float fmax = unflipf(ld_acq(&g_mm[s][1]));
            float S = 31.0f / (fmax - fmin + 1e-6f);
            g_sb[s] = make_float2(S, -fmin * S);
            g_mm[s ^ 1][0] = 0xFFFFFFFFu;               // next replay's slot
            g_mm[s ^ 1][1] = 0u;
            atomicExch(&g_count, 0u);
            __threadfence();
            atomicAdd(&g_release, 1u);
            s_SB[0] = S;
            s_SB[1] = -fmin * S;
        } else {
            while (ld_acq(&g_release) == epoch0) __nanosleep(16);
            float2 sb = g_sb[s];                        // ordered after acquire
            s_SB[0] = sb.x;
            s_SB[1] = sb.y;
        }
    }
    __syncthreads();
    const float S = s_SB[0];
    const float B = s_SB[1];

    // ------------------- phase 2: transform (reverse replay) --------------
    float4* __restrict__ o4 = (float4*)outs;
    {
        int j = jlast;
        // 1) SMEM-kept slots (no global reads)
        #pragma unroll
        for (int s = NKEEP - 1; s >= 0; s--) {
            if (j >= 0 && j >= keep_lo) {
                float4 v = skeep[s * NTHREADS + threadIdx.x];
                float4 r;
                r.x = auf_eval(v.x, S, B, tab);
                r.y = auf_eval(v.y, S, B, tab);
                r.z = auf_eval(v.z, S, B, tab);
                r.w = auf_eval(v.w, S, B, tab);
                __stcs(&o4[j], r);
                j -= stride;
            }
        }
        // 2) pinned window (L2 hits), then streaming region (DRAM)
        #pragma unroll 2
        for (; j >= 0; j -= stride) {
            float4 v = __ldcs(&x4[j]);
            float4 r;
            r.x = auf_eval(v.x, S, B, tab);
            r.y = auf_eval(v.y, S, B, tab);
            r.z = auf_eval(v.z, S, B, tab);
            r.w = auf_eval(v.w, S, B, tab);
            __stcs(&o4[j], r);
        }
    }
    if (blockIdx.x == 0 && threadIdx.x < (n & 3)) {     // scalar tail
        const int e = (nv4 << 2) + threadIdx.x;
        outs[e] = auf_eval(xs[e], S, B, tab);
    }
}

// ---------------------------------------------------------------------------
// Launch: ONE kernel + 24KB dynamic SMEM. No sync, no allocation.
// ---------------------------------------------------------------------------
extern "C" void kernel_launch(void* const* d_in, const int* in_sizes, int n_in,
                              void* d_out, int out_size) {
    const float* x  = (const float*)d_in[0];   // (64, 1048576) fp32
    const float* cp = (const float*)d_in[1];   // (32,) control points
    // d_in[2] = knots: uniform linspace(0,1,32) -> analytic, unused
    const int n = in_sizes[0];

    const size_t smem = (size_t)NKEEP * NTHREADS * sizeof(float4);  // 24 KB
    auf_fused_kernel<<<NPART, NTHREADS, smem>>>(x, cp, (float*)d_out, n);
}

// round 8
// speedup vs baseline: 1.0564x; 1.0564x over previous
#include <cuda_runtime.h>

// ---------------------------------------------------------------------------
// AdaptiveUnivariateFunction — fused persistent kernel (round 8).
//   xn = (x - min)/(max - min + 1e-6) in [0,1)
//   out = cp[idx] + t*(cp[idx+1]-cp[idx]),  idx=clamp(floor(xn*31),0,30)
//
// Skew-free schedule:
//   phase 1: [pinned 96MB tail: static, evict_last]  then
//            [160MB streaming: DYNAMIC 16KB chunks off atomic counter]
//            -> all blocks hit the barrier within ~1 chunk time.
//   phase 2: [pinned tail: static reverse replay -> L2 hits]  then
//            [streaming region: DYNAMIC chunks, 2nd counter]
//            -> kernel end equally balanced. DRAM-miss reads don't care
//               which block issues them, so redistribution is free.
// Counters/minmax ping-pong by barrier epoch; releaser resets alt slot.
// ---------------------------------------------------------------------------

#define NPART 1184               // 148 SMs x 8 blocks -> exactly one wave
#define NTHREADS 256
#define CHUNK_ITERS 4            // iterations per claimed chunk
#define CHUNK_V4 (CHUNK_ITERS * NTHREADS)   // 1024 float4 = 16 KB
#define PIN_V4 6291456           // 96 MB / 16 B pinned in L2

// ping-pong state; slot = epoch & 1
__device__ unsigned int g_mm[2][2] = {{0xFFFFFFFFu, 0u}, {0xFFFFFFFFu, 0u}};
__device__ float2 g_sb[2];                 // published (S, B)
__device__ unsigned int g_ctr1[2];         // phase-1 chunk counter
__device__ unsigned int g_ctr2[2];         // phase-2 chunk counter
__device__ unsigned int g_count;           // barrier arrivals
__device__ unsigned int g_release;         // barrier epoch (monotone)

__device__ __forceinline__ unsigned int ld_acq(const unsigned int* p) {
    unsigned int v;
    asm volatile("ld.global.acquire.gpu.u32 %0, [%1];" : "=r"(v) : "l"(p));
    return v;
}
__device__ __forceinline__ unsigned int flipf(float f) {
    unsigned int u = __float_as_uint(f);
    return u ^ ((unsigned int)(-(int)(u >> 31)) | 0x80000000u);
}
__device__ __forceinline__ float unflipf(unsigned int u) {
    return __uint_as_float(u ^ (((u >> 31) - 1u) | 0x80000000u));
}
__device__ __forceinline__ float4 ld_pin(const float4* p, unsigned long long pol) {
    float4 v;
    asm volatile("ld.global.L2::cache_hint.v4.f32 {%0,%1,%2,%3}, [%4], %5;"
                 : "=f"(v.x), "=f"(v.y), "=f"(v.z), "=f"(v.w)
                 : "l"(p), "l"(pol));
    return v;
}

__device__ __forceinline__ float auf_eval(float x, float S, float B,
                                          const float2* __restrict__ tab) {
    float xn31 = fmaf(x, S, B);            // xn * 31
    int idx = (int)xn31;                   // trunc == floor here
    idx = max(0, min(idx, 30));            // boundary rounding value-neutral
    float2 ad = tab[idx];                  // (cp[idx], cp[idx+1]-cp[idx])
    return fmaf(xn31 - (float)idx, ad.y, ad.x);
}

__global__ void __launch_bounds__(NTHREADS, 8)
auf_fused_kernel(const float* __restrict__ xs,
                 const float* __restrict__ cp,
                 float* __restrict__ outs,
                 int n) {
    __shared__ float2 tab[32];
    __shared__ float smin[8], smax[8];
    __shared__ float s_SB[2];
    __shared__ int s_chunk;

    // epoch/slot: only thread 0 uses them (atomics + claims)
    unsigned int epoch0 = 0;
    int slot = 0;
    if (threadIdx.x == 0) {
        epoch0 = ld_acq(&g_release);
        slot = (int)(epoch0 & 1u);
    }

    // spline table: (cp[i], cp[i+1]-cp[i]); slot 31 duplicates 30
    if (threadIdx.x < 32) {
        int i = (threadIdx.x < 31) ? (int)threadIdx.x : 30;
        float c0 = cp[i];
        float c1 = cp[i + 1];
        tab[threadIdx.x] = make_float2(c0, c1 - c0);
    }

    unsigned long long pol;
    asm volatile("createpolicy.fractional.L2::evict_last.b64 %0, 1.0;" : "=l"(pol));

    const float4* __restrict__ x4 = (const float4*)xs;
    const int nv4 = n >> 2;
    const int tid0 = blockIdx.x * NTHREADS + (int)threadIdx.x;
    const int stride = NPART * NTHREADS;

    // region split: dynamic chunks cover [0, pin_lo), static pinned [pin_lo, nv4)
    int dynv4 = nv4 - PIN_V4;
    if (dynv4 < 0) dynv4 = 0;
    const int nchunks = dynv4 / CHUNK_V4;
    const int pin_lo = nchunks * CHUNK_V4;

    // ------------------- phase 1: min/max -------------------
    float vmin = 3.402823466e38f;
    float vmax = -3.402823466e38f;

    // (a) static pinned tail first: all blocks start together
    {
        int i = tid0;
        if (pin_lo > tid0)
            i = tid0 + ((pin_lo - tid0 + stride - 1) / stride) * stride;
        #pragma unroll 4
        for (; i < nv4; i += stride) {
            float4 v = ld_pin(&x4[i], pol);
            vmin = fminf(vmin, fminf(fminf(v.x, v.y), fminf(v.z, v.w)));
            vmax = fmaxf(vmax, fmaxf(fmaxf(v.x, v.y), fmaxf(v.z, v.w)));
        }
    }
    // (b) dynamic chunks over streaming region (prefetched claims)
    if (threadIdx.x == 0) s_chunk = (int)atomicAdd(&g_ctr1[slot], 1u);
    __syncthreads();
    {
        int cur = s_chunk;
        while (cur < nchunks) {
            if (threadIdx.x == 0)                    // claim next, overlapped
                s_chunk = (int)atomicAdd(&g_ctr1[slot], 1u);
            const int base = cur * CHUNK_V4 + (int)threadIdx.x;
            #pragma unroll
            for (int u = 0; u < CHUNK_ITERS; u++) {
                float4 v = __ldcs(&x4[base + u * NTHREADS]);
                vmin = fminf(vmin, fminf(fminf(v.x, v.y), fminf(v.z, v.w)));
                vmax = fmaxf(vmax, fmaxf(fmaxf(v.x, v.y), fmaxf(v.z, v.w)));
            }
            __syncthreads();                         // s_chunk update visible
            cur = s_chunk;
        }
    }
    if (blockIdx.x == 0 && threadIdx.x < (n & 3)) {  // scalar tail (defensive)
        float v = xs[(nv4 << 2) + threadIdx.x];
        vmin = fminf(vmin, v);
        vmax = fmaxf(vmax, v);
    }

    #pragma unroll
    for (int o = 16; o; o >>= 1) {
        vmin = fminf(vmin, __shfl_xor_sync(0xFFFFFFFFu, vmin, o));
        vmax = fmaxf(vmax, __shfl_xor_sync(0xFFFFFFFFu, vmax, o));
    }
    const int wid = threadIdx.x >> 5;
    if ((threadIdx.x & 31) == 0) { smin[wid] = vmin; smax[wid] = vmax; }
    __syncthreads();

    // ------------------- barrier with folded reduction -------------------
    if (threadIdx.x == 0) {
        float bmin = smin[0], bmax = smax[0];
        #pragma unroll
        for (int w = 1; w < 8; w++) {
            bmin = fminf(bmin, smin[w]);
            bmax = fmaxf(bmax, smax[w]);
        }
        atomicMin(&g_mm[slot][0], flipf(bmin));
        atomicMax(&g_mm[slot][1], flipf(bmax));
        __threadfence();
        unsigned int old = atomicAdd(&g_count, 1u);
        if (old == NPART - 1) {
            // last arrival: finalize, publish, reset alternate-slot state
            float fmin = unflipf(ld_acq(&g_mm[slot][0]));
            float fmax = unflipf(ld_acq(&g_mm[slot][1]));
            float S = 31.0f / (fmax - fmin + 1e-6f);
            g_sb[slot] = make_float2(S, -fmin * S);
            g_mm[slot ^ 1][0] = 0xFFFFFFFFu;         // next replay's slot
            g_mm[slot ^ 1][1] = 0u;
            g_ctr1[slot ^ 1] = 0u;
            g_ctr2[slot ^ 1] = 0u;
            atomicExch(&g_count, 0u);
            __threadfence();
            atomicAdd(&g_release, 1u);
            s_SB[0] = S;
            s_SB[1] = -fmin * S;
        } else {
            while (ld_acq(&g_release) == epoch0) __nanosleep(16);
            float2 sb = g_sb[slot];                  // ordered after acquire
            s_SB[0] = sb.x;
            s_SB[1] = sb.y;
        }
    }
    __syncthreads();
    const float S = s_SB[0];
    const float B = s_SB[1];

    // ------------------- phase 2: transform -------------------
    float4* __restrict__ o4 = (float4*)outs;

    // (a) static pinned tail, REVERSE own-index replay -> L2 hits
    if (tid0 < nv4) {
        const int jlast = tid0 + ((nv4 - 1 - tid0) / stride) * stride;
        #pragma unroll 2
        for (int j = jlast; j >= pin_lo; j -= stride) {
            float4 v = __ldcs(&x4[j]);               // pinned line; demote
            float4 r;
            r.x = auf_eval(v.x, S, B, tab);
            r.y = auf_eval(v.y, S, B, tab);
            r.z = auf_eval(v.z, S, B, tab);
            r.w = auf_eval(v.w, S, B, tab);
            __stcs(&o4[j], r);
        }
    }
    // (b) dynamic chunks over streaming region (DRAM either way)
    if (threadIdx.x == 0) s_chunk = (int)atomicAdd(&g_ctr2[slot], 1u);
    __syncthreads();
    {
        int cur = s_chunk;
        while (cur < nchunks) {
            if (threadIdx.x == 0)
                s_chunk = (int)atomicAdd(&g_ctr2[slot], 1u);
            const int base = cur * CHUNK_V4 + (int)threadIdx.x;
            #pragma unroll
            for (int u = 0; u < CHUNK_ITERS; u++) {
                const int j = base + u * NTHREADS;
                float4 v = __ldcs(&x4[j]);
                float4 r;
                r.x = auf_eval(v.x, S, B, tab);
                r.y = auf_eval(v.y, S, B, tab);
                r.z = auf_eval(v.z, S, B, tab);
                r.w = auf_eval(v.w, S, B, tab);
                __stcs(&o4[j], r);
            }
            __syncthreads();
            cur = s_chunk;
        }
    }
    if (blockIdx.x == 0 && threadIdx.x < (n & 3)) {  // scalar tail
        const int e = (nv4 << 2) + threadIdx.x;
        outs[e] = auf_eval(xs[e], S, B, tab);
    }
}

// ---------------------------------------------------------------------------
// Launch: ONE kernel. No sync, no allocation -> graph-capturable.
// ---------------------------------------------------------------------------
extern "C" void kernel_launch(void* const* d_in, const int* in_sizes, int n_in,
                              void* d_out, int out_size) {
    const float* x  = (const float*)d_in[0];   // (64, 1048576) fp32
    const float* cp = (const float*)d_in[1];   // (32,) control points
    // d_in[2] = knots: uniform linspace(0,1,32) -> analytic, unused
    const int n = in_sizes[0];

    auf_fused_kernel<<<NPART, NTHREADS>>>(x, cp, (float*)d_out, n);
}

// round 9
// speedup vs baseline: 1.1171x; 1.0575x over previous
#include <cuda_runtime.h>

// ---------------------------------------------------------------------------
// AdaptiveUnivariateFunction — fused persistent kernel (round 9).
//   xn = (x - min)/(max - min + 1e-6) in [0,1)
//   out = cp[idx] + t*(cp[idx+1]-cp[idx]),  idx=clamp(floor(xn*31),0,30)
//
// No L2 policy hints (evict_last poisons steady-state replays). Natural LRU
// keeps the freshest ~96MB. Schedule:
//   phase 1: DYNAMIC 16KB chunks over the first 160MB (.cs, absorbs skew),
//            then STATIC 96MB tail with default loads (fresh at barrier).
//   phase 2: STATIC tail reverse replay (natural L2 hits),
//            then DYNAMIC chunks over the rest (balanced finish).
// Counters/minmax ping-pong by barrier epoch; releaser resets alt slot.
// ---------------------------------------------------------------------------

#define NPART 1184               // 148 SMs x 8 blocks -> exactly one wave
#define NTHREADS 256
#define CHUNK_ITERS 4            // iterations per claimed chunk
#define CHUNK_V4 (CHUNK_ITERS * NTHREADS)   // 1024 float4 = 16 KB
#define TAIL_V4 6291456          // 96 MB / 16 B static tail (L2-fresh)

// ping-pong state; slot = epoch & 1
__device__ unsigned int g_mm[2][2] = {{0xFFFFFFFFu, 0u}, {0xFFFFFFFFu, 0u}};
__device__ float2 g_sb[2];                 // published (S, B)
__device__ unsigned int g_ctr1[2];         // phase-1 chunk counter
__device__ unsigned int g_ctr2[2];         // phase-2 chunk counter
__device__ unsigned int g_count;           // barrier arrivals
__device__ unsigned int g_release;         // barrier epoch (monotone)

__device__ __forceinline__ unsigned int ld_acq(const unsigned int* p) {
    unsigned int v;
    asm volatile("ld.global.acquire.gpu.u32 %0, [%1];" : "=r"(v) : "l"(p));
    return v;
}
__device__ __forceinline__ unsigned int flipf(float f) {
    unsigned int u = __float_as_uint(f);
    return u ^ ((unsigned int)(-(int)(u >> 31)) | 0x80000000u);
}
__device__ __forceinline__ float unflipf(unsigned int u) {
    return __uint_as_float(u ^ (((u >> 31) - 1u) | 0x80000000u));
}

__device__ __forceinline__ float auf_eval(float x, float S, float B,
                                          const float2* __restrict__ tab) {
    float xn31 = fmaf(x, S, B);            // xn * 31
    int idx = (int)xn31;                   // trunc == floor here
    idx = max(0, min(idx, 30));            // boundary rounding value-neutral
    float2 ad = tab[idx];                  // (cp[idx], cp[idx+1]-cp[idx])
    return fmaf(xn31 - (float)idx, ad.y, ad.x);
}

__global__ void __launch_bounds__(NTHREADS, 8)
auf_fused_kernel(const float* __restrict__ xs,
                 const float* __restrict__ cp,
                 float* __restrict__ outs,
                 int n) {
    __shared__ float2 tab[32];
    __shared__ float smin[8], smax[8];
    __shared__ float s_SB[2];
    __shared__ int s_chunk;

    // epoch/slot: only thread 0 uses them (atomics + claims)
    unsigned int epoch0 = 0;
    int slot = 0;
    if (threadIdx.x == 0) {
        epoch0 = ld_acq(&g_release);
        slot = (int)(epoch0 & 1u);
    }

    // spline table: (cp[i], cp[i+1]-cp[i]); slot 31 duplicates 30
    if (threadIdx.x < 32) {
        int i = (threadIdx.x < 31) ? (int)threadIdx.x : 30;
        float c0 = cp[i];
        float c1 = cp[i + 1];
        tab[threadIdx.x] = make_float2(c0, c1 - c0);
    }

    const float4* __restrict__ x4 = (const float4*)xs;
    const int nv4 = n >> 2;
    const int tid0 = blockIdx.x * NTHREADS + (int)threadIdx.x;
    const int stride = NPART * NTHREADS;

    // region split: dynamic chunks over [0, tail_lo), static tail [tail_lo, nv4)
    int dynv4 = nv4 - TAIL_V4;
    if (dynv4 < 0) dynv4 = 0;
    const int nchunks = dynv4 / CHUNK_V4;
    const int tail_lo = nchunks * CHUNK_V4;

    // ------------------- phase 1: min/max -------------------
    float vmin = 3.402823466e38f;
    float vmax = -3.402823466e38f;

    // (a) DYNAMIC chunks over streaming region (.cs; prefetched claims)
    if (threadIdx.x == 0) s_chunk = (int)atomicAdd(&g_ctr1[slot], 1u);
    __syncthreads();
    {
        int cur = s_chunk;
        while (cur < nchunks) {
            if (threadIdx.x == 0)                    // claim next, overlapped
                s_chunk = (int)atomicAdd(&g_ctr1[slot], 1u);
            const int base = cur * CHUNK_V4 + (int)threadIdx.x;
            #pragma unroll
            for (int u = 0; u < CHUNK_ITERS; u++) {
                float4 v = __ldcs(&x4[base + u * NTHREADS]);
                vmin = fminf(vmin, fminf(fminf(v.x, v.y), fminf(v.z, v.w)));
                vmax = fmaxf(vmax, fmaxf(fmaxf(v.x, v.y), fmaxf(v.z, v.w)));
            }
            __syncthreads();                         // s_chunk update visible
            cur = s_chunk;
        }
    }
    // (b) STATIC tail last: default loads -> freshest lines in L2 at barrier
    {
        int i = tid0;
        if (tail_lo > tid0)
            i = tid0 + ((tail_lo - tid0 + stride - 1) / stride) * stride;
        #pragma unroll 4
        for (; i < nv4; i += stride) {
            float4 v = x4[i];
            vmin = fminf(vmin, fminf(fminf(v.x, v.y), fminf(v.z, v.w)));
            vmax = fmaxf(vmax, fmaxf(fmaxf(v.x, v.y), fmaxf(v.z, v.w)));
        }
    }
    if (blockIdx.x == 0 && threadIdx.x < (n & 3)) {  // scalar tail (defensive)
        float v = xs[(nv4 << 2) + threadIdx.x];
        vmin = fminf(vmin, v);
        vmax = fmaxf(vmax, v);
    }

    #pragma unroll
    for (int o = 16; o; o >>= 1) {
        vmin = fminf(vmin, __shfl_xor_sync(0xFFFFFFFFu, vmin, o));
        vmax = fmaxf(vmax, __shfl_xor_sync(0xFFFFFFFFu, vmax, o));
    }
    const int wid = threadIdx.x >> 5;
    if ((threadIdx.x & 31) == 0) { smin[wid] = vmin; smax[wid] = vmax; }
    __syncthreads();

    // ------------------- barrier with folded reduction -------------------
    if (threadIdx.x == 0) {
        float bmin = smin[0], bmax = smax[0];
        #pragma unroll
        for (int w = 1; w < 8; w++) {
            bmin = fminf(bmin, smin[w]);
            bmax = fmaxf(bmax, smax[w]);
        }
        atomicMin(&g_mm[slot][0], flipf(bmin));
        atomicMax(&g_mm[slot][1], flipf(bmax));
        __threadfence();
        unsigned int old = atomicAdd(&g_count, 1u);
        if (old == NPART - 1) {
            // last arrival: finalize, publish, reset alternate-slot state
            float fmin = unflipf(ld_acq(&g_mm[slot][0]));
            float fmax = unflipf(ld_acq(&g_mm[slot][1]));
            float S = 31.0f / (fmax - fmin + 1e-6f);
            g_sb[slot] = make_float2(S, -fmin * S);
            g_mm[slot ^ 1][0] = 0xFFFFFFFFu;         // next replay's slot
            g_mm[slot ^ 1][1] = 0u;
            g_ctr1[slot ^ 1] = 0u;
            g_ctr2[slot ^ 1] = 0u;
            atomicExch(&g_count, 0u);
            __threadfence();
            atomicAdd(&g_release, 1u);
            s_SB[0] = S;
            s_SB[1] = -fmin * S;
        } else {
            while (ld_acq(&g_release) == epoch0) __nanosleep(16);
            float2 sb = g_sb[slot];                  // ordered after acquire
            s_SB[0] = sb.x;
            s_SB[1] = sb.y;
        }
    }
    __syncthreads();
    const float S = s_SB[0];
    const float B = s_SB[1];

    // ------------------- phase 2: transform -------------------
    float4* __restrict__ o4 = (float4*)outs;

    // (a) STATIC tail, REVERSE own-index replay -> natural L2 hits
    if (tid0 < nv4) {
        const int jlast = tid0 + ((nv4 - 1 - tid0) / stride) * stride;
        #pragma unroll 2
        for (int j = jlast; j >= tail_lo; j -= stride) {
            float4 v = __ldcs(&x4[j]);               // hit; demote residue
            float4 r;
            r.x = auf_eval(v.x, S, B, tab);
            r.y = auf_eval(v.y, S, B, tab);
            r.z = auf_eval(v.z, S, B, tab);
            r.w = auf_eval(v.w, S, B, tab);
            __stcs(&o4[j], r);
        }
    }
    // (b) DYNAMIC chunks over streaming region (DRAM either way)
    if (threadIdx.x == 0) s_chunk = (int)atomicAdd(&g_ctr2[slot], 1u);
    __syncthreads();
    {
        int cur = s_chunk;
        while (cur < nchunks) {
            if (threadIdx.x == 0)
                s_chunk = (int)atomicAdd(&g_ctr2[slot], 1u);
            const int base = cur * CHUNK_V4 + (int)threadIdx.x;
            #pragma unroll
            for (int u = 0; u < CHUNK_ITERS; u++) {
                const int j = base + u * NTHREADS;
                float4 v = __ldcs(&x4[j]);
                float4 r;
                r.x = auf_eval(v.x, S, B, tab);
                r.y = auf_eval(v.y, S, B, tab);
                r.z = auf_eval(v.z, S, B, tab);
                r.w = auf_eval(v.w, S, B, tab);
                __stcs(&o4[j], r);
            }
            __syncthreads();
            cur = s_chunk;
        }
    }
    if (blockIdx.x == 0 && threadIdx.x < (n & 3)) {  // scalar tail
        const int e = (nv4 << 2) + threadIdx.x;
        outs[e] = auf_eval(xs[e], S, B, tab);
    }
}

// ---------------------------------------------------------------------------
// Launch: ONE kernel. No sync, no allocation -> graph-capturable.
// ---------------------------------------------------------------------------
extern "C" void kernel_launch(void* const* d_in, const int* in_sizes, int n_in,
                              void* d_out, int out_size) {
    const float* x  = (const float*)d_in[0];   // (64, 1048576) fp32
    const float* cp = (const float*)d_in[1];   // (32,) control points
    // d_in[2] = knots: uniform linspace(0,1,32) -> analytic, unused
    const int n = in_sizes[0];

    auf_fused_kernel<<<NPART, NTHREADS>>>(x, cp, (float*)d_out, n);
}